// round 12
// baseline (speedup 1.0000x reference)
#include <cuda_runtime.h>
#include <cstdint>

// Gated delta rule: S_t = S_{t-1} @ A_t + B_t.  T=128, 64 chains, D=64.
// R12 = R11 + `asm volatile` on all ordering-critical shared loads.
// R11 bug: non-volatile ld.shared asm (pure function of address at NVVM level)
// could be hoisted above __syncthreads, reading stale partial sums.
//
// Design: 128 CTAs (2/chain, 32 rows) x 128 threads (4 warps). Warp w computes
// partial P_w = sum_{k in [16w,16w+16)} over the full 32x64 tile (8x8/thread).
// Tree reduction: w1->Pa, w3->Pb | sync | w0+=Pa, w2+=Pb->Pb, w1/w3 store out
// | sync | w0+=Pb+Bm -> Snext.  ~1792 smem wavefronts/step (R6 had ~2432).

#define T_DIM 128
#define BH 64
#define D 64
#define ROWS 32
#define THREADS 128
#define TSTRIDE (BH * D * D)

#define AB_BYTES 16384              // [k][j] 64x64 f32, 256B per k
#define SB_BYTES 8192               // [k][r] 64x32 f32, 128B per k
#define AB0_OFF 0
#define AB1_OFF 16384
#define SB0_OFF 32768
#define SB1_OFF 40960
#define PA_OFF  49152
#define PB_OFF  57344
#define SMEM_BYTES 65536

__device__ __forceinline__ uint32_t smem_u32(const void* p) {
    return (uint32_t)__cvta_generic_to_shared(p);
}
__device__ __forceinline__ unsigned long long pk2(float lo, float hi) {
    unsigned long long r;
    asm("mov.b64 %0,{%1,%2};" : "=l"(r) : "f"(lo), "f"(hi));
    return r;
}
__device__ __forceinline__ unsigned long long f2fma(unsigned long long a,
                                                    unsigned long long b,
                                                    unsigned long long c) {
    unsigned long long d;
    asm("fma.rn.f32x2 %0,%1,%2,%3;" : "=l"(d) : "l"(a), "l"(b), "l"(c));
    return d;
}
__device__ __forceinline__ unsigned long long f2add(unsigned long long a,
                                                    unsigned long long b) {
    unsigned long long d;
    asm("add.rn.f32x2 %0,%1,%2;" : "=l"(d) : "l"(a), "l"(b));
    return d;
}

__global__ void __launch_bounds__(THREADS, 1) gdr_kernel(
    const float* __restrict__ A,
    const float* __restrict__ Bm,
    const float* __restrict__ S0,
    float* __restrict__ out)
{
    extern __shared__ char smem[];
    const uint32_t SMB = smem_u32(smem);

    const int tid  = threadIdx.x;
    const int lane = tid & 31;
    const int wid  = tid >> 5;
    const int rg   = lane >> 3;      // row group: rows 8rg..8rg+7
    const int cg   = lane & 7;       // col group: cols 8cg..8cg+7
    const int kb   = wid * 16;       // this warp's k range

    const int chain = blockIdx.x >> 1;
    const int half  = blockIdx.x & 1;
    const int r0base = half * ROWS;
    const long chainOff = (long)chain * (D * D);

    const uint32_t tileOff = (uint32_t)(cg * 8 * 128 + rg * 32);

    // ---- prologue: A[0] via cp.async (linear [k][j]) ----
    {
        uint32_t s = SMB + AB0_OFF + tid * 16;
        const float* g = A + chainOff + tid * 4;
        #pragma unroll
        for (int i = 0; i < 8; i++) {
            asm volatile("cp.async.cg.shared.global [%0],[%1],16;"
                         :: "r"(s + i * 2048), "l"(g + i * 512));
        }
        asm volatile("cp.async.commit_group;");
    }

    // Init Sb0[k*32 + r] = S0[r][k]
    {
        float* Sb0f = (float*)(smem + SB0_OFF);
        int rl = tid & 31;
        int kk0 = (tid >> 5) * 16;
        const float* g = S0 + chainOff + (long)(r0base + rl) * D + kk0;
        #pragma unroll
        for (int kk = 0; kk < 16; kk++)
            Sb0f[(kk0 + kk) * 32 + rl] = g[kk];
    }

    // ---- main time loop ----
    for (int t = 0; t < T_DIM; t++) {
        asm volatile("cp.async.wait_group 0;" ::: "memory");
        __syncthreads();   // A[t], S_{t-1} ready; S_t buffer free

        const int cur = t & 1;
        const uint32_t Acur  = SMB + (cur ? AB1_OFF : AB0_OFF);
        const uint32_t Anext = SMB + (cur ? AB0_OFF : AB1_OFF);
        const uint32_t Scur  = SMB + (cur ? SB1_OFF : SB0_OFF);
        const uint32_t Snext = SMB + (cur ? SB0_OFF : SB1_OFF);
        const uint32_t Pa = SMB + PA_OFF;
        const uint32_t Pb = SMB + PB_OFF;

        // prefetch A[t+1]
        if (t + 1 < T_DIM) {
            uint32_t s = Anext + tid * 16;
            const float* g = A + (long)(t + 1) * TSTRIDE + chainOff + tid * 4;
            #pragma unroll
            for (int i = 0; i < 8; i++) {
                asm volatile("cp.async.cg.shared.global [%0],[%1],16;"
                             :: "r"(s + i * 2048), "l"(g + i * 512));
            }
            asm volatile("cp.async.commit_group;");
        }

        // accumulators: 4 row-pairs x 8 cols, start at zero (Bm added at end)
        unsigned long long acc[4][8];
        #pragma unroll
        for (int p = 0; p < 4; p++)
            #pragma unroll
            for (int j = 0; j < 8; j++) acc[p][j] = 0ull;

        // ---- k-loop: this warp's 16 k's, 8x8 tile ----
        {
            const uint32_t sB = Scur + kb * 128 + rg * 32;
            const uint32_t aB = Acur + kb * 256 + cg * 32;
            #pragma unroll
            for (int k2 = 0; k2 < 16; k2++) {
                unsigned long long s01, s23, s45, s67;
                asm volatile("ld.shared.v2.u64 {%0,%1},[%2];"
                    : "=l"(s01), "=l"(s23) : "r"(sB + k2 * 128));
                asm volatile("ld.shared.v2.u64 {%0,%1},[%2];"
                    : "=l"(s45), "=l"(s67) : "r"(sB + k2 * 128 + 16));
                float a0, a1, a2, a3, a4, a5, a6, a7;
                asm volatile("ld.shared.v4.f32 {%0,%1,%2,%3},[%4];"
                    : "=f"(a0), "=f"(a1), "=f"(a2), "=f"(a3)
                    : "r"(aB + k2 * 256));
                asm volatile("ld.shared.v4.f32 {%0,%1,%2,%3},[%4];"
                    : "=f"(a4), "=f"(a5), "=f"(a6), "=f"(a7)
                    : "r"(aB + k2 * 256 + 16));
                float av[8] = {a0, a1, a2, a3, a4, a5, a6, a7};
                #pragma unroll
                for (int j = 0; j < 8; j++) {
                    unsigned long long d = pk2(av[j], av[j]);
                    acc[0][j] = f2fma(s01, d, acc[0][j]);
                    acc[1][j] = f2fma(s23, d, acc[1][j]);
                    acc[2][j] = f2fma(s45, d, acc[2][j]);
                    acc[3][j] = f2fma(s67, d, acc[3][j]);
                }
            }
        }

        // warp0: issue Bm loads now (latency hidden by reduction phase)
        float4 bmv[8][2];
        if (wid == 0) {
            const float* g = Bm + (long)t * TSTRIDE + chainOff
                           + (long)(r0base + rg * 8) * D + cg * 8;
            #pragma unroll
            for (int rr = 0; rr < 8; rr++) {
                bmv[rr][0] = *(const float4*)(g + rr * D);
                bmv[rr][1] = *(const float4*)(g + rr * D + 4);
            }
        }

        // w1 -> Pa, w3 -> Pb (partials in [c][r] layout)
        if (wid == 1 || wid == 3) {
            uint32_t p = (wid == 1 ? Pa : Pb) + tileOff;
            #pragma unroll
            for (int j = 0; j < 8; j++) {
                asm volatile("st.shared.v2.u64 [%0],{%1,%2};"
                             :: "r"(p + j * 128), "l"(acc[0][j]), "l"(acc[1][j]));
                asm volatile("st.shared.v2.u64 [%0],{%1,%2};"
                             :: "r"(p + j * 128 + 16), "l"(acc[2][j]), "l"(acc[3][j]));
            }
        }
        __syncthreads();

        if (wid == 0 || wid == 2) {
            // round 1: w0 += Pa, w2 += Pb; then w2 re-stores its sum to Pb
            uint32_t p = (wid == 0 ? Pa : Pb) + tileOff;
            #pragma unroll
            for (int j = 0; j < 8; j++) {
                unsigned long long x0, x1, x2, x3;
                asm volatile("ld.shared.v2.u64 {%0,%1},[%2];"
                    : "=l"(x0), "=l"(x1) : "r"(p + j * 128));
                asm volatile("ld.shared.v2.u64 {%0,%1},[%2];"
                    : "=l"(x2), "=l"(x3) : "r"(p + j * 128 + 16));
                acc[0][j] = f2add(acc[0][j], x0);
                acc[1][j] = f2add(acc[1][j], x1);
                acc[2][j] = f2add(acc[2][j], x2);
                acc[3][j] = f2add(acc[3][j], x3);
            }
            if (wid == 2) {
                uint32_t q = Pb + tileOff;
                #pragma unroll
                for (int j = 0; j < 8; j++) {
                    asm volatile("st.shared.v2.u64 [%0],{%1,%2};"
                                 :: "r"(q + j * 128), "l"(acc[0][j]), "l"(acc[1][j]));
                    asm volatile("st.shared.v2.u64 [%0],{%1,%2};"
                                 :: "r"(q + j * 128 + 16), "l"(acc[2][j]), "l"(acc[3][j]));
                }
            }
        } else if (t > 0) {
            // w1, w3: out-store S_{t-1} from Scur ([c][r] -> row-major gmem)
            int u = (wid == 1 ? 0 : 32) + lane;   // 0..63
            int r = u >> 1;
            int ch = u & 1;                        // col half (32 cols)
            float v[32];
            #pragma unroll
            for (int j = 0; j < 32; j++) {
                asm volatile("ld.shared.f32 %0,[%1];" : "=f"(v[j])
                    : "r"(Scur + (32 * ch + j) * 128 + r * 4));
            }
            float* o = out + (long)(t - 1) * TSTRIDE + chainOff
                     + (long)(r0base + r) * D + 32 * ch;
            #pragma unroll
            for (int i = 0; i < 8; i++)
                *(float4*)(o + i * 4) = make_float4(v[4*i], v[4*i+1],
                                                    v[4*i+2], v[4*i+3]);
        }
        __syncthreads();

        // round 2: w0 += Pb, += Bm, write S_t -> Snext ([c][r] layout)
        if (wid == 0) {
            uint32_t p = Pb + tileOff;
            #pragma unroll
            for (int j = 0; j < 8; j++) {
                unsigned long long x0, x1, x2, x3;
                asm volatile("ld.shared.v2.u64 {%0,%1},[%2];"
                    : "=l"(x0), "=l"(x1) : "r"(p + j * 128));
                asm volatile("ld.shared.v2.u64 {%0,%1},[%2];"
                    : "=l"(x2), "=l"(x3) : "r"(p + j * 128 + 16));
                acc[0][j] = f2add(acc[0][j], x0);
                acc[1][j] = f2add(acc[1][j], x1);
                acc[2][j] = f2add(acc[2][j], x2);
                acc[3][j] = f2add(acc[3][j], x3);
            }
            // += Bm (row pairs 2p,2p+1 -> bmv rows)
            #pragma unroll
            for (int p4 = 0; p4 < 4; p4++) {
                const float4 u0 = bmv[2 * p4][0],     u1 = bmv[2 * p4][1];
                const float4 w0 = bmv[2 * p4 + 1][0], w1 = bmv[2 * p4 + 1][1];
                acc[p4][0] = f2add(acc[p4][0], pk2(u0.x, w0.x));
                acc[p4][1] = f2add(acc[p4][1], pk2(u0.y, w0.y));
                acc[p4][2] = f2add(acc[p4][2], pk2(u0.z, w0.z));
                acc[p4][3] = f2add(acc[p4][3], pk2(u0.w, w0.w));
                acc[p4][4] = f2add(acc[p4][4], pk2(u1.x, w1.x));
                acc[p4][5] = f2add(acc[p4][5], pk2(u1.y, w1.y));
                acc[p4][6] = f2add(acc[p4][6], pk2(u1.z, w1.z));
                acc[p4][7] = f2add(acc[p4][7], pk2(u1.w, w1.w));
            }
            uint32_t s = Snext + tileOff;
            #pragma unroll
            for (int j = 0; j < 8; j++) {
                asm volatile("st.shared.v2.u64 [%0],{%1,%2};"
                             :: "r"(s + j * 128), "l"(acc[0][j]), "l"(acc[1][j]));
                asm volatile("st.shared.v2.u64 [%0],{%1,%2};"
                             :: "r"(s + j * 128 + 16), "l"(acc[2][j]), "l"(acc[3][j]));
            }
        }
        // next iteration's top __syncthreads publishes Snext
    }

    // ---- final out-store for t = T-1 (state in Sb0: cur=1 at t=127) ----
    __syncthreads();
    {
        const uint32_t Slast = SMB + SB0_OFF;
        int r = tid >> 2;
        int q = tid & 3;                 // 16-col quarter
        float v[16];
        #pragma unroll
        for (int j = 0; j < 16; j++) {
            asm volatile("ld.shared.f32 %0,[%1];" : "=f"(v[j])
                : "r"(Slast + (16 * q + j) * 128 + r * 4));
        }
        float* o = out + (long)(T_DIM - 1) * TSTRIDE + chainOff
                 + (long)(r0base + r) * D + 16 * q;
        #pragma unroll
        for (int i = 0; i < 4; i++)
            *(float4*)(o + i * 4) = make_float4(v[4*i], v[4*i+1],
                                                v[4*i+2], v[4*i+3]);
    }
}

extern "C" void kernel_launch(void* const* d_in, const int* in_sizes, int n_in,
                              void* d_out, int out_size) {
    const float* A  = (const float*)d_in[0];
    const float* Bm = (const float*)d_in[1];
    const float* S0 = (const float*)d_in[2];
    float* out = (float*)d_out;
    (void)in_sizes; (void)n_in; (void)out_size;

    cudaFuncSetAttribute(gdr_kernel,
                         cudaFuncAttributeMaxDynamicSharedMemorySize,
                         SMEM_BYTES);
    gdr_kernel<<<BH * 2, THREADS, SMEM_BYTES>>>(A, Bm, S0, out);
}